// round 8
// baseline (speedup 1.0000x reference)
#include <cuda_runtime.h>
#include <math.h>

// Sampler: Gumbel-keys relaxed top-k. khot = sum_{t=1..k} softmax(att_g_t),
// att_g_{t+1} = att_g_t + log(max(1 - onehot_t, eps)).
// One CTA per row (B=128 rows, n=1024), all state in registers. The kernel is
// latency-CHAIN bound (128 independent rows, 1 per SM) -> minimize barrier
// round-trips:
//  (1) fixed softmax shift M0 (logits monotone non-increasing), computed once.
//  (2) unnormalized numerators: oh = e/S; acc += oh; e <- e*(1-oh).
//  (3) DEPTH-3 STEP FUSION via moments (S, P2, P3, P4 = sums of e^1..e^4):
//        S2 = S - P2/S
//        Q2 = sum e'^2 = P2 - (2*P3 - P4/S)/S      (exact algebra)
//        S3 = S2 - Q2/S2
//      -> 3 softmax steps per ONE barrier round-trip. The Q2 form cancels
//      quadratically when one element dominates, so the 3rd step is gated on
//      participation ratio P2 < 0.9*S^2 (block-uniform). Errors are one-shot:
//      every sync re-reduces exact sums from the e registers.

#define NTHREADS 256
#define NWARPS   (NTHREADS / 32)
#define NNODES   1024
#define EPT      (NNODES / NTHREADS)   // 4
#define EPS_F    1.1754943508222875e-38f  // np.finfo(float32).tiny
#define LOG2E    1.4426950408889634f

__device__ __forceinline__ float ex2_approx(float x) {
    float r; asm("ex2.approx.f32 %0, %1;" : "=f"(r) : "f"(x)); return r;
}
__device__ __forceinline__ float rcp_approx(float x) {
    float r; asm("rcp.approx.f32 %0, %1;" : "=f"(r) : "f"(x)); return r;
}
__device__ __forceinline__ float4 add4(float4 a, float4 b) {
    return make_float4(a.x + b.x, a.y + b.y, a.z + b.z, a.w + b.w);
}

__global__ __launch_bounds__(NTHREADS, 1)
void sampler_topk_kernel(const float* __restrict__ att,
                         const float* __restrict__ uni,
                         const int*  __restrict__ kptr,
                         float* __restrict__ out)
{
    // per-warp moment vectors (S,P2,P3,P4), double-buffered: one barrier per
    // sync is race-free (write buf(t+2) is after bar(t+1); reads of buf(t)
    // sit between bar(t) and bar(t+1)).
    __shared__ __align__(16) float4 sm4[2][NWARPS];
    __shared__ __align__(16) float  sm_m[NWARPS];

    const int row  = blockIdx.x;
    const int tid  = threadIdx.x;
    const int lane = tid & 31;
    const int warp = tid >> 5;
    const int k    = *kptr;

    const float* __restrict__ arow = att + row * NNODES;
    const float* __restrict__ urow = uni + row * NNODES;
    float*       __restrict__ orow = out + row * NNODES;

    float b[EPT], e[EPT], acc[EPT];

    // Gumbel init in log2 domain: b = (att - log(-log(u+eps))) * log2(e)
    float m = -3.402823466e38f;
    #pragma unroll
    for (int j = 0; j < EPT; ++j) {
        const int idx = tid + j * NTHREADS;          // coalesced
        float u = urow[idx];
        b[j] = (arow[idx] - logf(-logf(u + EPS_F))) * LOG2E;
        m = fmaxf(m, b[j]);
        acc[j] = 0.0f;
    }
    // one-time block max M0 (valid shift forever: logits only decrease)
    #pragma unroll
    for (int o = 16; o > 0; o >>= 1)
        m = fmaxf(m, __shfl_xor_sync(0xffffffffu, m, o));
    if (lane == 0) sm_m[warp] = m;
    __syncthreads();
    {
        float4 m0 = *(const float4*)&sm_m[0];
        float4 m1 = *(const float4*)&sm_m[4];
        float M = fmaxf(fmaxf(fmaxf(m0.x, m0.y), fmaxf(m0.z, m0.w)),
                        fmaxf(fmaxf(m1.x, m1.y), fmaxf(m1.z, m1.w)));
        #pragma unroll
        for (int j = 0; j < EPT; ++j)
            e[j] = ex2_approx(b[j] - M);             // unnormalized numerators
    }

    int steps_left = k;
    int it = 0;
    while (steps_left > 0) {
        // ---- local moments: s, p2, p3, p4 ----
        float s = 0.f, p2 = 0.f, p3 = 0.f, p4 = 0.f;
        #pragma unroll
        for (int j = 0; j < EPT; ++j) {
            float x  = e[j];
            float x2 = x * x;
            s  += x;
            p2 += x2;
            p3 += x2 * x;
            p4 += x2 * x2;
        }
        // ---- 4-wide interleaved warp butterflies ----
        #pragma unroll
        for (int o = 16; o > 0; o >>= 1) {
            s  += __shfl_xor_sync(0xffffffffu, s,  o);
            p2 += __shfl_xor_sync(0xffffffffu, p2, o);
            p3 += __shfl_xor_sync(0xffffffffu, p3, o);
            p4 += __shfl_xor_sync(0xffffffffu, p4, o);
        }
        const int buf = it & 1;
        if (lane == 0) sm4[buf][warp] = make_float4(s, p2, p3, p4);
        __syncthreads();
        const float4* sv = &sm4[buf][0];
        float4 t = add4(add4(add4(sv[0], sv[1]), add4(sv[2], sv[3])),
                        add4(add4(sv[4], sv[5]), add4(sv[6], sv[7])));
        const float S = t.x, P2 = t.y, P3 = t.z, P4 = t.w;

        // ---- round A: scale = 1/S ----
        float rA = rcp_approx(S);
        #pragma unroll
        for (int j = 0; j < EPT; ++j) {
            float oh = e[j] * rA;
            acc[j] += oh;
            e[j] = __fmaf_rn(-oh, e[j], e[j]);       // e*(1-oh)
        }
        steps_left -= 1;

        if (steps_left > 0) {
            // ---- round B: S2 = S - P2/S ----
            float S2 = __fmaf_rn(-P2, rA, S);
            S2 = fmaxf(S2, S * 1e-6f);
            float rB = rcp_approx(S2);
            #pragma unroll
            for (int j = 0; j < EPT; ++j) {
                float oh = e[j] * rB;
                acc[j] += oh;
                e[j] = __fmaf_rn(-oh, e[j], e[j]);
            }
            steps_left -= 1;

            // ---- round C (gated): S3 = S2 - Q2/S2 ----
            if (steps_left > 0 && P2 < 0.9f * (S * S)) {
                float u  = __fmaf_rn(-P4, rA, 2.0f * P3);  // 2*P3 - P4/S
                float Q2 = __fmaf_rn(-u, rA, P2);          // P2 - u/S
                Q2 = fmaxf(Q2, 0.0f);
                float S3 = __fmaf_rn(-Q2, rB, S2);
                S3 = fmaxf(S3, S2 * 1e-6f);
                float rC = rcp_approx(S3);
                #pragma unroll
                for (int j = 0; j < EPT; ++j) {
                    float oh = e[j] * rC;
                    acc[j] += oh;
                    e[j] = __fmaf_rn(-oh, e[j], e[j]);
                }
                steps_left -= 1;
            }
        }
        ++it;
    }

    #pragma unroll
    for (int j = 0; j < EPT; ++j)
        orow[tid + j * NTHREADS] = acc[j];
}

extern "C" void kernel_launch(void* const* d_in, const int* in_sizes, int n_in,
                              void* d_out, int out_size)
{
    const float* att = (const float*)d_in[0];
    const float* uni = (const float*)d_in[1];
    const int*   kp  = (const int*)d_in[2];
    float* out = (float*)d_out;

    const int B = in_sizes[0] / NNODES;   // 128
    sampler_topk_kernel<<<B, NTHREADS>>>(att, uni, kp, out);
}

// round 9
// speedup vs baseline: 1.2380x; 1.2380x over previous
#include <cuda_runtime.h>
#include <math.h>

// Sampler: Gumbel-keys relaxed top-k. khot = sum_{t=1..k} softmax(att_g_t),
// att_g_{t+1} = att_g_t + log(max(1 - onehot_t, eps)).
// One CTA per row (B=128 rows, n=1024), all state in registers. Latency-chain
// bound -> minimize barrier round-trips AND shuffle-throughput pressure:
//  (1) fixed softmax shift M0 (logits monotone non-increasing), computed once.
//  (2) unnormalized numerators: oh = e/S; acc += oh; e <- e*(1-oh).
//  (3) DEPTH-3 STEP FUSION via moments (S,P2,P3,P4):
//        S2 = S - P2/S;  Q2 = P2 - (2*P3 - P4/S)/S;  S3 = S2 - Q2/S2
//      gated on participation P2 < 0.9*S^2 (block-uniform). One-shot error:
//      every sync re-reduces exact sums from the e registers.
//  (4) 128 threads / 4 warps (1 per SMSP): halves SHFL/MIO pressure that made
//      depth-3 neutral at 256 threads; spare issue slots absorb EPT=8.

#define NTHREADS 128
#define NWARPS   (NTHREADS / 32)       // 4
#define NNODES   1024
#define EPT      (NNODES / NTHREADS)   // 8
#define EPS_F    1.1754943508222875e-38f  // np.finfo(float32).tiny
#define LOG2E    1.4426950408889634f

__device__ __forceinline__ float ex2_approx(float x) {
    float r; asm("ex2.approx.f32 %0, %1;" : "=f"(r) : "f"(x)); return r;
}
__device__ __forceinline__ float rcp_approx(float x) {
    float r; asm("rcp.approx.f32 %0, %1;" : "=f"(r) : "f"(x)); return r;
}
__device__ __forceinline__ float4 add4(float4 a, float4 b) {
    return make_float4(a.x + b.x, a.y + b.y, a.z + b.z, a.w + b.w);
}

__global__ __launch_bounds__(NTHREADS, 1)
void sampler_topk_kernel(const float* __restrict__ att,
                         const float* __restrict__ uni,
                         const int*  __restrict__ kptr,
                         float* __restrict__ out)
{
    // per-warp moment vectors (S,P2,P3,P4), double-buffered: one barrier per
    // sync is race-free (write of buf(t+2) is after bar(t+1); reads of buf(t)
    // sit between bar(t) and bar(t+1)).
    __shared__ __align__(16) float4 sm4[2][NWARPS];
    __shared__ __align__(16) float  sm_m[NWARPS];

    const int row  = blockIdx.x;
    const int tid  = threadIdx.x;
    const int lane = tid & 31;
    const int warp = tid >> 5;
    const int k    = *kptr;

    const float* __restrict__ arow = att + row * NNODES;
    const float* __restrict__ urow = uni + row * NNODES;
    float*       __restrict__ orow = out + row * NNODES;

    float e[EPT], acc[EPT];

    // Gumbel init in log2 domain: b = (att - log(-log(u+eps))) * log2(e)
    {
        float b[EPT];
        float m = -3.402823466e38f;
        #pragma unroll
        for (int j = 0; j < EPT; ++j) {
            const int idx = tid + j * NTHREADS;      // coalesced
            float u = urow[idx];
            b[j] = (arow[idx] - logf(-logf(u + EPS_F))) * LOG2E;
            m = fmaxf(m, b[j]);
            acc[j] = 0.0f;
        }
        // one-time block max M0 (valid shift forever: logits only decrease)
        #pragma unroll
        for (int o = 16; o > 0; o >>= 1)
            m = fmaxf(m, __shfl_xor_sync(0xffffffffu, m, o));
        if (lane == 0) sm_m[warp] = m;
        __syncthreads();
        float4 mv = *(const float4*)&sm_m[0];
        float M = fmaxf(fmaxf(mv.x, mv.y), fmaxf(mv.z, mv.w));
        #pragma unroll
        for (int j = 0; j < EPT; ++j)
            e[j] = ex2_approx(b[j] - M);             // unnormalized numerators
    }

    int steps_left = k;
    int it = 0;
    while (steps_left > 0) {
        // ---- local moments: s, p2, p3, p4 (FMA-fused) ----
        float s = 0.f, p2 = 0.f, p3 = 0.f, p4 = 0.f;
        #pragma unroll
        for (int j = 0; j < EPT; ++j) {
            float x  = e[j];
            float x2 = x * x;
            s  += x;
            p2 = __fmaf_rn(x,  x,  p2);
            p3 = __fmaf_rn(x2, x,  p3);
            p4 = __fmaf_rn(x2, x2, p4);
        }
        // ---- 4-wide interleaved warp butterflies (1 warp per SMSP) ----
        #pragma unroll
        for (int o = 16; o > 0; o >>= 1) {
            s  += __shfl_xor_sync(0xffffffffu, s,  o);
            p2 += __shfl_xor_sync(0xffffffffu, p2, o);
            p3 += __shfl_xor_sync(0xffffffffu, p3, o);
            p4 += __shfl_xor_sync(0xffffffffu, p4, o);
        }
        const int buf = it & 1;
        if (lane == 0) sm4[buf][warp] = make_float4(s, p2, p3, p4);
        __syncthreads();
        const float4* sv = &sm4[buf][0];
        float4 t = add4(add4(sv[0], sv[1]), add4(sv[2], sv[3]));
        const float S = t.x, P2 = t.y, P3 = t.z, P4 = t.w;

        // ---- round A: scale = 1/S ----
        float rA = rcp_approx(S);
        #pragma unroll
        for (int j = 0; j < EPT; ++j) {
            float oh = e[j] * rA;
            acc[j] += oh;
            e[j] = __fmaf_rn(-oh, e[j], e[j]);       // e*(1-oh)
        }
        steps_left -= 1;

        if (steps_left > 0) {
            // ---- round B: S2 = S - P2/S ----
            float S2 = __fmaf_rn(-P2, rA, S);
            S2 = fmaxf(S2, S * 1e-6f);
            float rB = rcp_approx(S2);
            #pragma unroll
            for (int j = 0; j < EPT; ++j) {
                float oh = e[j] * rB;
                acc[j] += oh;
                e[j] = __fmaf_rn(-oh, e[j], e[j]);
            }
            steps_left -= 1;

            // ---- round C (gated): S3 = S2 - Q2/S2 ----
            if (steps_left > 0 && P2 < 0.9f * (S * S)) {
                float u  = __fmaf_rn(-P4, rA, 2.0f * P3);  // 2*P3 - P4/S
                float Q2 = __fmaf_rn(-u, rA, P2);          // P2 - u/S
                Q2 = fmaxf(Q2, 0.0f);
                float S3 = __fmaf_rn(-Q2, rB, S2);
                S3 = fmaxf(S3, S2 * 1e-6f);
                float rC = rcp_approx(S3);
                #pragma unroll
                for (int j = 0; j < EPT; ++j) {
                    float oh = e[j] * rC;
                    acc[j] += oh;
                    e[j] = __fmaf_rn(-oh, e[j], e[j]);
                }
                steps_left -= 1;
            }
        }
        ++it;
    }

    #pragma unroll
    for (int j = 0; j < EPT; ++j)
        orow[tid + j * NTHREADS] = acc[j];
}

extern "C" void kernel_launch(void* const* d_in, const int* in_sizes, int n_in,
                              void* d_out, int out_size)
{
    const float* att = (const float*)d_in[0];
    const float* uni = (const float*)d_in[1];
    const int*   kp  = (const int*)d_in[2];
    float* out = (float*)d_out;

    const int B = in_sizes[0] / NNODES;   // 128
    sampler_topk_kernel<<<B, NTHREADS>>>(att, uni, kp, out);
}